// round 6
// baseline (speedup 1.0000x reference)
#include <cuda_runtime.h>
#include <cstdint>
#include <math.h>

#define FULL 0xffffffffu

static constexpr int B_   = 256;
static constexpr int D_   = 128;
static constexpr int DIN_ = 2048;
static constexpr int M_   = 4096;
static constexpr float TAU_INV = 1.0f / 0.07f;

// ---------------- device scratch ----------------
__device__ float4 g_emb[B_ * (D_ / 4)];   // normalized embeddings, 128 KB
__device__ float  g_acc[2];               // [0]=sum data softplus, [1]=sum noise softplus

// ---------------- cluster helpers (raw PTX, sm_90+) ----------------
__device__ __forceinline__ void cluster_sync_() {
    asm volatile("barrier.cluster.arrive.aligned;" ::: "memory");
    asm volatile("barrier.cluster.wait.aligned;" ::: "memory");
}
__device__ __forceinline__ unsigned mapa_shared_(unsigned smem_addr, unsigned rank) {
    unsigned r;
    asm("mapa.shared::cluster.u32 %0, %1, %2;" : "=r"(r) : "r"(smem_addr), "r"(rank));
    return r;
}
__device__ __forceinline__ float ld_shared_cluster_f32_(unsigned addr) {
    float v;
    asm volatile("ld.shared::cluster.f32 %0, [%1];" : "=f"(v) : "r"(addr));
    return v;
}

// ---------------- A: fused GEMM + bias + L2-normalize ------------------------
// grid 256 = 64 b-groups (4 rows) x 4 d-groups (32 cols), cluster of 4 over d.
// 512 threads = 16 warps; warp w owns 2 d-cols; 2 blocks/SM for latency hiding.
__global__ void __cluster_dims__(4, 1, 1) __launch_bounds__(512, 2)
kGemmNorm(const float* __restrict__ outputs,
          const float* __restrict__ W,
          const float* __restrict__ bias) {
    int bg = blockIdx.x >> 2;   // 0..63
    int dg = blockIdx.x & 3;    // 0..3 == cluster rank
    int tid = threadIdx.x, w = tid >> 5, lane = tid & 31;

    __shared__ float so[4][1024];     // K-chunk of the 4 output rows (16 KB)
    __shared__ float semb[4][32];     // emb_raw+bias for our 32 d-cols
    __shared__ float s_partial[4];    // partial sum-of-squares per b
    __shared__ float s_nsq[4];        // full sum-of-squares per b

    int d0 = dg * 32 + w * 2;         // warp's first global d (owns d0, d0+1)

    float acc[2][4];
#pragma unroll
    for (int dd = 0; dd < 2; dd++)
#pragma unroll
        for (int bb = 0; bb < 4; bb++) acc[dd][bb] = 0.0f;

    const float4* o4 = (const float4*)outputs;
    const float4* w4 = (const float4*)W;

#pragma unroll
    for (int chunk = 0; chunk < 2; chunk++) {
        // stage 4 output rows, k in [chunk*1024, chunk*1024+1024)
        for (int i = tid; i < 4 * 256; i += 512) {
            int bb = i >> 8, c = i & 255;
            ((float4*)so[bb])[c] =
                o4[(size_t)(bg * 4 + bb) * (DIN_ / 4) + chunk * 256 + c];
        }
        __syncthreads();

#pragma unroll
        for (int it = 0; it < 8; it++) {
            int kg4 = (chunk * 1024 + it * 128) / 4 + lane;  // float4 idx in W row
            float4 wv[2];
#pragma unroll
            for (int dd = 0; dd < 2; dd++)
                wv[dd] = w4[(size_t)(d0 + dd) * (DIN_ / 4) + kg4];
#pragma unroll
            for (int bb = 0; bb < 4; bb++) {
                float4 ov = ((const float4*)so[bb])[it * 32 + lane];
#pragma unroll
                for (int dd = 0; dd < 2; dd++) {
                    float a = acc[dd][bb];
                    a = fmaf(wv[dd].x, ov.x, a);
                    a = fmaf(wv[dd].y, ov.y, a);
                    a = fmaf(wv[dd].z, ov.z, a);
                    a = fmaf(wv[dd].w, ov.w, a);
                    acc[dd][bb] = a;
                }
            }
        }
        __syncthreads();
    }

    // butterfly-reduce each of the 8 accumulators; lane dd*4+bb keeps it
    float mine = 0.0f;
#pragma unroll
    for (int dd = 0; dd < 2; dd++)
#pragma unroll
        for (int bb = 0; bb < 4; bb++) {
            float r = acc[dd][bb];
#pragma unroll
            for (int o = 16; o; o >>= 1) r += __shfl_xor_sync(FULL, r, o);
            if (lane == dd * 4 + bb) mine = r;
        }
    if (lane < 8) {
        int dd = lane >> 2, bloc = lane & 3;
        int dloc = w * 2 + dd;                 // 0..31 local d
        semb[bloc][dloc] = mine + bias[dg * 32 + dloc];
    }
    __syncthreads();

    // partial sum-of-squares: warp w (<4) reduces b-row w
    if (w < 4) {
        float v = semb[w][lane];
        float ss = v * v;
#pragma unroll
        for (int o = 16; o; o >>= 1) ss += __shfl_xor_sync(FULL, ss, o);
        if (lane == 0) s_partial[w] = ss;
    }
    cluster_sync_();

    // combine 4 cluster ranks' partials via DSMEM
    if (tid < 4) {
        unsigned sp = (unsigned)__cvta_generic_to_shared(s_partial) + tid * 4;
        float nsq = 0.0f;
#pragma unroll
        for (unsigned rr = 0; rr < 4; rr++)
            nsq += ld_shared_cluster_f32_(mapa_shared_(sp, rr));
        s_nsq[tid] = nsq;
    }
    __syncthreads();

    // normalize + write our d-slice of g_emb (128 threads cover 4b x 32d)
    if (tid < 128) {
        int b = tid & 3, dl = tid >> 2;   // dl 0..31
        float inv = 1.0f / fmaxf(sqrtf(s_nsq[b]), 1e-12f);
        ((float*)g_emb)[(size_t)(bg * 4 + b) * D_ + dg * 32 + dl] =
            semb[b][dl] * inv;
    }
    if (blockIdx.x == 0 && tid == 0) { g_acc[0] = 0.0f; g_acc[1] = 0.0f; }
    cluster_sync_();   // keep smem alive until all peers finished reading
}

// ---------------- B: main gather + logsumexp + losses + entries --------------
// One block per batch row. 16 warps; warp w handles negs [w*256, w*256+256).
// Paired-row reduction: 5 shfls per 2 rows; indices via smem broadcast.
__global__ void __launch_bounds__(512, 2) kMain(
    const float* __restrict__ mbank,
    const int*   __restrict__ indices,
    const int*   __restrict__ ridx,
    float*       __restrict__ out) {
    int b = blockIdx.x;
    int tid = threadIdx.x, w = tid >> 5, lane = tid & 31;

    __shared__ float sneg[M_];
    __shared__ int   sidx[M_];
    __shared__ float sr[33];

    // stage this block's 4096 indices (coalesced int4)
    {
        const int4* ri4 = (const int4*)(ridx + (size_t)b * M_);
        int4* si4 = (int4*)sidx;
        for (int i = tid; i < M_ / 4; i += 512) si4[i] = ri4[i];
    }

    float4 e = g_emb[b * 32 + lane];
    const float4* mb4 = (const float4*)mbank;
    __syncthreads();

    // ---- gather + dot: 256 negs per warp, processed in pairs ----
    int m0 = w * 256;
#pragma unroll 4
    for (int j = m0; j < m0 + 256; j += 2) {
        int idx0 = sidx[j];          // LDS broadcast
        int idx1 = sidx[j + 1];
        float4 v0 = mb4[(size_t)idx0 * 32 + lane];
        float4 v1 = mb4[(size_t)idx1 * 32 + lane];
        float da = v0.x * e.x + v0.y * e.y;
        da = fmaf(v0.z, e.z, da);
        da = fmaf(v0.w, e.w, da);
        float db = v1.x * e.x + v1.y * e.y;
        db = fmaf(v1.z, e.z, db);
        db = fmaf(v1.w, e.w, db);
        // parity swap: even lanes accumulate row j, odd lanes row j+1
        bool odd = (lane & 1);
        float x = odd ? db : da;
        float y = odd ? da : db;
        x += __shfl_xor_sync(FULL, y, 1);
#pragma unroll
        for (int o = 2; o <= 16; o <<= 1) x += __shfl_xor_sync(FULL, x, o);
        // even lanes hold S(j), odd lanes hold S(j+1)
        int jl = j & 31;                       // even
        if (lane == jl)     sneg[j]     = x * TAU_INV;
        if (lane == jl + 1) sneg[j + 1] = x * TAU_INV;
    }
    __syncthreads();

    // ---- each thread owns 8 negs (stride 512, conflict-free) ----
    float vl[8];
    float mx = -3.0e38f;
#pragma unroll
    for (int i = 0; i < 8; i++) {
        vl[i] = sneg[tid + i * 512];
        mx = fmaxf(mx, vl[i]);
    }
#pragma unroll
    for (int o = 16; o; o >>= 1) mx = fmaxf(mx, __shfl_xor_sync(FULL, mx, o));
    if (lane == 0) sr[w] = mx;
    __syncthreads();
    if (w == 0) {
        float t2 = sr[lane & 15];
#pragma unroll
        for (int o = 8; o; o >>= 1) t2 = fmaxf(t2, __shfl_xor_sync(FULL, t2, o));
        if (lane == 0) sr[32] = t2;
    }
    __syncthreads();
    float Mx = sr[32];

    float se = 0.f;
#pragma unroll
    for (int i = 0; i < 8; i++) se += __expf(vl[i] - Mx);
#pragma unroll
    for (int o = 16; o; o >>= 1) se += __shfl_xor_sync(FULL, se, o);
    __syncthreads();
    if (lane == 0) sr[w] = se;
    __syncthreads();
    if (w == 0) {
        float t2 = (lane < 16) ? sr[lane] : 0.f;
#pragma unroll
        for (int o = 8; o; o >>= 1) t2 += __shfl_xor_sync(FULL, t2, o);
        if (lane == 0) sr[32] = Mx + __logf(t2);
    }
    __syncthreads();
    float logC = sr[32];

    // noise loss: sum softplus(neg - logC)
    float ns = 0.f;
#pragma unroll
    for (int i = 0; i < 8; i++) {
        float x = vl[i] - logC;
        ns += (x > 15.f) ? x : log1pf(__expf(x));
    }
#pragma unroll
    for (int o = 16; o; o >>= 1) ns += __shfl_xor_sync(FULL, ns, o);
    __syncthreads();
    if (lane == 0) sr[w] = ns;
    __syncthreads();
    if (w == 0) {
        float t2 = (lane < 16) ? sr[lane] : 0.f;
#pragma unroll
        for (int o = 8; o; o >>= 1) t2 += __shfl_xor_sync(FULL, t2, o);
        if (lane == 0) atomicAdd(&g_acc[1], t2);
    }

    // ---- warp 0: positive term + entries ----
    if (w == 0) {
        int pidx = indices[b];
        float4 p = mb4[(size_t)pidx * 32 + lane];
        float d = p.x * e.x + p.y * e.y;
        d = fmaf(p.z, e.z, d);
        d = fmaf(p.w, e.w, d);
#pragma unroll
        for (int o = 16; o; o >>= 1) d += __shfl_xor_sync(FULL, d, o);
        float pos = d * TAU_INV;

        float4 ent;
        ent.x = 0.5f * (p.x + e.x);
        ent.y = 0.5f * (p.y + e.y);
        ent.z = 0.5f * (p.z + e.z);
        ent.w = 0.5f * (p.w + e.w);
        float nsq = ent.x * ent.x + ent.y * ent.y + ent.z * ent.z + ent.w * ent.w;
#pragma unroll
        for (int o = 16; o; o >>= 1) nsq += __shfl_xor_sync(FULL, nsq, o);
        float inv = 1.0f / fmaxf(sqrtf(nsq), 1e-12f);
        ent.x *= inv; ent.y *= inv; ent.z *= inv; ent.w *= inv;

        int base = 1 + b * D_ + lane * 4;
        out[base + 0] = ent.x;
        out[base + 1] = ent.y;
        out[base + 2] = ent.z;
        out[base + 3] = ent.w;

        if (lane == 0) {
            float x = logC - pos;
            float dl = (x > 15.f) ? x : log1pf(__expf(x));
            atomicAdd(&g_acc[0], dl);
        }
    }
}

// ---------------- C: finalize scalars ----------------------------------------
__global__ void kFinal(float* __restrict__ out) {
    float dl = g_acc[0] * (1.0f / (float)B_);
    float nl = g_acc[1] * (1.0f / (float)B_);
    out[0] = dl + nl;
    out[1 + B_ * D_]     = dl;
    out[1 + B_ * D_ + 1] = nl;
}

// ---------------- launcher ----------------------------------------------------
extern "C" void kernel_launch(void* const* d_in, const int* in_sizes, int n_in,
                              void* d_out, int out_size) {
    const float* outputs = (const float*)d_in[0];
    const float* W       = (const float*)d_in[1];
    const float* bias    = (const float*)d_in[2];
    const float* mbank   = (const float*)d_in[3];
    const int*   indices = (const int*)d_in[4];
    const int*   ridx    = (const int*)d_in[5];
    float* out = (float*)d_out;

    kGemmNorm<<<256, 512>>>(outputs, W, bias);
    kMain<<<256, 512>>>(mbank, indices, ridx, out);
    kFinal<<<1, 1>>>(out);
}

// round 7
// speedup vs baseline: 1.2389x; 1.2389x over previous
#include <cuda_runtime.h>
#include <cstdint>
#include <math.h>

#define FULL 0xffffffffu

static constexpr int B_   = 256;
static constexpr int D_   = 128;
static constexpr int DIN_ = 2048;
static constexpr int M_   = 4096;
static constexpr float TAU_INV = 1.0f / 0.07f;

// ---------------- device scratch ----------------
__device__ float4 g_emb[B_ * (D_ / 4)];   // normalized embeddings, 128 KB
__device__ float  g_acc[2];               // [0]=sum data softplus, [1]=sum noise softplus

// ---------------- cluster helpers (raw PTX, sm_90+) ----------------
__device__ __forceinline__ void cluster_sync_() {
    asm volatile("barrier.cluster.arrive.aligned;" ::: "memory");
    asm volatile("barrier.cluster.wait.aligned;" ::: "memory");
}
__device__ __forceinline__ unsigned mapa_shared_(unsigned smem_addr, unsigned rank) {
    unsigned r;
    asm("mapa.shared::cluster.u32 %0, %1, %2;" : "=r"(r) : "r"(smem_addr), "r"(rank));
    return r;
}
__device__ __forceinline__ float ld_shared_cluster_f32_(unsigned addr) {
    float v;
    asm volatile("ld.shared::cluster.f32 %0, [%1];" : "=f"(v) : "r"(addr));
    return v;
}

// ---------------- A: fused GEMM + bias + L2-normalize ------------------------
// grid 256 = 64 b-groups (4 rows) x 4 d-groups (32 cols), cluster of 4 over d.
// 512 threads = 16 warps; warp w owns 2 d-cols; 2 blocks/SM for latency hiding.
__global__ void __cluster_dims__(4, 1, 1) __launch_bounds__(512, 2)
kGemmNorm(const float* __restrict__ outputs,
          const float* __restrict__ W,
          const float* __restrict__ bias) {
    int bg = blockIdx.x >> 2;   // 0..63
    int dg = blockIdx.x & 3;    // 0..3 == cluster rank
    int tid = threadIdx.x, w = tid >> 5, lane = tid & 31;

    __shared__ float so[4][1024];     // K-chunk of the 4 output rows (16 KB)
    __shared__ float semb[4][32];     // emb_raw+bias for our 32 d-cols
    __shared__ float s_partial[4];    // partial sum-of-squares per b
    __shared__ float s_nsq[4];        // full sum-of-squares per b

    int d0 = dg * 32 + w * 2;         // warp's first global d (owns d0, d0+1)

    float acc[2][4];
#pragma unroll
    for (int dd = 0; dd < 2; dd++)
#pragma unroll
        for (int bb = 0; bb < 4; bb++) acc[dd][bb] = 0.0f;

    const float4* o4 = (const float4*)outputs;
    const float4* w4 = (const float4*)W;

#pragma unroll
    for (int chunk = 0; chunk < 2; chunk++) {
        // stage 4 output rows, k in [chunk*1024, chunk*1024+1024)
        for (int i = tid; i < 4 * 256; i += 512) {
            int bb = i >> 8, c = i & 255;
            ((float4*)so[bb])[c] =
                o4[(size_t)(bg * 4 + bb) * (DIN_ / 4) + chunk * 256 + c];
        }
        __syncthreads();

#pragma unroll
        for (int it = 0; it < 8; it++) {
            int kg4 = (chunk * 1024 + it * 128) / 4 + lane;  // float4 idx in W row
            float4 wv[2];
#pragma unroll
            for (int dd = 0; dd < 2; dd++)
                wv[dd] = w4[(size_t)(d0 + dd) * (DIN_ / 4) + kg4];
#pragma unroll
            for (int bb = 0; bb < 4; bb++) {
                float4 ov = ((const float4*)so[bb])[it * 32 + lane];
#pragma unroll
                for (int dd = 0; dd < 2; dd++) {
                    float a = acc[dd][bb];
                    a = fmaf(wv[dd].x, ov.x, a);
                    a = fmaf(wv[dd].y, ov.y, a);
                    a = fmaf(wv[dd].z, ov.z, a);
                    a = fmaf(wv[dd].w, ov.w, a);
                    acc[dd][bb] = a;
                }
            }
        }
        __syncthreads();
    }

    // butterfly-reduce each of the 8 accumulators; lane dd*4+bb keeps it
    float mine = 0.0f;
#pragma unroll
    for (int dd = 0; dd < 2; dd++)
#pragma unroll
        for (int bb = 0; bb < 4; bb++) {
            float r = acc[dd][bb];
#pragma unroll
            for (int o = 16; o; o >>= 1) r += __shfl_xor_sync(FULL, r, o);
            if (lane == dd * 4 + bb) mine = r;
        }
    if (lane < 8) {
        int dd = lane >> 2, bloc = lane & 3;
        int dloc = w * 2 + dd;                 // 0..31 local d
        semb[bloc][dloc] = mine + bias[dg * 32 + dloc];
    }
    __syncthreads();

    // partial sum-of-squares: warp w (<4) reduces b-row w
    if (w < 4) {
        float v = semb[w][lane];
        float ss = v * v;
#pragma unroll
        for (int o = 16; o; o >>= 1) ss += __shfl_xor_sync(FULL, ss, o);
        if (lane == 0) s_partial[w] = ss;
    }
    cluster_sync_();

    // combine 4 cluster ranks' partials via DSMEM
    if (tid < 4) {
        unsigned sp = (unsigned)__cvta_generic_to_shared(s_partial) + tid * 4;
        float nsq = 0.0f;
#pragma unroll
        for (unsigned rr = 0; rr < 4; rr++)
            nsq += ld_shared_cluster_f32_(mapa_shared_(sp, rr));
        s_nsq[tid] = nsq;
    }
    __syncthreads();

    // normalize + write our d-slice of g_emb (128 threads cover 4b x 32d)
    if (tid < 128) {
        int b = tid & 3, dl = tid >> 2;   // dl 0..31
        float inv = 1.0f / fmaxf(sqrtf(s_nsq[b]), 1e-12f);
        ((float*)g_emb)[(size_t)(bg * 4 + b) * D_ + dg * 32 + dl] =
            semb[b][dl] * inv;
    }
    if (blockIdx.x == 0 && tid == 0) { g_acc[0] = 0.0f; g_acc[1] = 0.0f; }
    cluster_sync_();   // keep smem alive until all peers finished reading
}

// ---------------- B: main gather + logsumexp + losses + entries --------------
// One block per batch row. 16 warps; warp w handles negs [w*256, w*256+256).
// (R4 version: shfl idx broadcast, unroll 8 gather, no fences.)
__global__ void __launch_bounds__(512, 2) kMain(
    const float* __restrict__ mbank,
    const int*   __restrict__ indices,
    const int*   __restrict__ ridx,
    float*       __restrict__ out) {
    int b = blockIdx.x;
    int tid = threadIdx.x, w = tid >> 5, lane = tid & 31;

    __shared__ float sneg[M_];
    __shared__ float sr[33];

    float4 e = g_emb[b * 32 + lane];
    const float4* mb4 = (const float4*)mbank;
    const int* ri = ridx + (size_t)b * M_;

    // ---- gather + dot: 256 negs per warp ----
    int m0 = w * 256;
    for (int mb_ = m0; mb_ < m0 + 256; mb_ += 32) {
        int myIdx = ri[mb_ + lane];
#pragma unroll 8
        for (int j = 0; j < 32; j++) {
            int idx = __shfl_sync(FULL, myIdx, j);
            float4 v = mb4[(size_t)idx * 32 + lane];
            float d = v.x * e.x + v.y * e.y;
            d = fmaf(v.z, e.z, d);
            d = fmaf(v.w, e.w, d);
#pragma unroll
            for (int o = 16; o; o >>= 1) d += __shfl_xor_sync(FULL, d, o);
            if (lane == j) sneg[mb_ + j] = d * TAU_INV;
        }
    }
    __syncthreads();

    // ---- each thread owns 8 negs (stride 512, conflict-free) ----
    float vl[8];
    float mx = -3.0e38f;
#pragma unroll
    for (int i = 0; i < 8; i++) {
        vl[i] = sneg[tid + i * 512];
        mx = fmaxf(mx, vl[i]);
    }
#pragma unroll
    for (int o = 16; o; o >>= 1) mx = fmaxf(mx, __shfl_xor_sync(FULL, mx, o));
    if (lane == 0) sr[w] = mx;
    __syncthreads();
    if (w == 0) {
        float t2 = sr[lane & 15];
#pragma unroll
        for (int o = 8; o; o >>= 1) t2 = fmaxf(t2, __shfl_xor_sync(FULL, t2, o));
        if (lane == 0) sr[32] = t2;
    }
    __syncthreads();
    float Mx = sr[32];

    float se = 0.f;
#pragma unroll
    for (int i = 0; i < 8; i++) se += __expf(vl[i] - Mx);
#pragma unroll
    for (int o = 16; o; o >>= 1) se += __shfl_xor_sync(FULL, se, o);
    __syncthreads();
    if (lane == 0) sr[w] = se;
    __syncthreads();
    if (w == 0) {
        float t2 = (lane < 16) ? sr[lane] : 0.f;
#pragma unroll
        for (int o = 8; o; o >>= 1) t2 += __shfl_xor_sync(FULL, t2, o);
        if (lane == 0) sr[32] = Mx + __logf(t2);
    }
    __syncthreads();
    float logC = sr[32];

    // noise loss: sum softplus(neg - logC)
    float ns = 0.f;
#pragma unroll
    for (int i = 0; i < 8; i++) {
        float x = vl[i] - logC;
        ns += (x > 15.f) ? x : log1pf(__expf(x));
    }
#pragma unroll
    for (int o = 16; o; o >>= 1) ns += __shfl_xor_sync(FULL, ns, o);
    __syncthreads();
    if (lane == 0) sr[w] = ns;
    __syncthreads();
    if (w == 0) {
        float t2 = (lane < 16) ? sr[lane] : 0.f;
#pragma unroll
        for (int o = 8; o; o >>= 1) t2 += __shfl_xor_sync(FULL, t2, o);
        if (lane == 0) atomicAdd(&g_acc[1], t2);
    }

    // ---- warp 0: positive term + entries ----
    if (w == 0) {
        int pidx = indices[b];
        float4 p = mb4[(size_t)pidx * 32 + lane];
        float d = p.x * e.x + p.y * e.y;
        d = fmaf(p.z, e.z, d);
        d = fmaf(p.w, e.w, d);
#pragma unroll
        for (int o = 16; o; o >>= 1) d += __shfl_xor_sync(FULL, d, o);
        float pos = d * TAU_INV;

        float4 ent;
        ent.x = 0.5f * (p.x + e.x);
        ent.y = 0.5f * (p.y + e.y);
        ent.z = 0.5f * (p.z + e.z);
        ent.w = 0.5f * (p.w + e.w);
        float nsq = ent.x * ent.x + ent.y * ent.y + ent.z * ent.z + ent.w * ent.w;
#pragma unroll
        for (int o = 16; o; o >>= 1) nsq += __shfl_xor_sync(FULL, nsq, o);
        float inv = 1.0f / fmaxf(sqrtf(nsq), 1e-12f);
        ent.x *= inv; ent.y *= inv; ent.z *= inv; ent.w *= inv;

        int base = 1 + b * D_ + lane * 4;
        out[base + 0] = ent.x;
        out[base + 1] = ent.y;
        out[base + 2] = ent.z;
        out[base + 3] = ent.w;

        if (lane == 0) {
            float x = logC - pos;
            float dl = (x > 15.f) ? x : log1pf(__expf(x));
            atomicAdd(&g_acc[0], dl);
        }
    }
}

// ---------------- C: finalize scalars ----------------------------------------
__global__ void kFinal(float* __restrict__ out) {
    float dl = g_acc[0] * (1.0f / (float)B_);
    float nl = g_acc[1] * (1.0f / (float)B_);
    out[0] = dl + nl;
    out[1 + B_ * D_]     = dl;
    out[1 + B_ * D_ + 1] = nl;
}

// ---------------- launcher ----------------------------------------------------
extern "C" void kernel_launch(void* const* d_in, const int* in_sizes, int n_in,
                              void* d_out, int out_size) {
    const float* outputs = (const float*)d_in[0];
    const float* W       = (const float*)d_in[1];
    const float* bias    = (const float*)d_in[2];
    const float* mbank   = (const float*)d_in[3];
    const int*   indices = (const int*)d_in[4];
    const int*   ridx    = (const int*)d_in[5];
    float* out = (float*)d_out;

    kGemmNorm<<<256, 512>>>(outputs, W, bias);
    kMain<<<256, 512>>>(mbank, indices, ridx, out);
    kFinal<<<1, 1>>>(out);
}

// round 8
// speedup vs baseline: 1.2677x; 1.0232x over previous
#include <cuda_runtime.h>
#include <cstdint>
#include <math.h>

#define FULL 0xffffffffu

static constexpr int B_   = 256;
static constexpr int D_   = 128;
static constexpr int DIN_ = 2048;
static constexpr int M_   = 4096;
static constexpr float TAU_INV = 1.0f / 0.07f;

// ---------------- device scratch ----------------
__device__ float g_raw[B_ * D_];        // un-normalized emb (+bias), 128 KB
__device__ float g_pssq[B_ * 16];       // per-d-slice partial sum-of-squares
__device__ float g_acc[2];              // [0]=sum data softplus, [1]=sum noise softplus

// ---------------- A: GEMM with W slice in SMEM -------------------------------
// grid 128 = 16 d-slices (8 cols) x 8 b-groups (32 rows). 256 threads = 8 warps.
// Warp w owns 4 b-rows x all 8 d-cols; lanes sweep K via float4.
// W slice (8 x 2048 fp32 = 64 KB) staged once in dynamic smem.
__global__ void __launch_bounds__(256, 2)
kGemm(const float* __restrict__ outputs,
      const float* __restrict__ W,
      const float* __restrict__ bias) {
    extern __shared__ float4 sW4[];       // [8][512] float4 = 64 KB
    int ds  = blockIdx.x & 15;            // d-slice 0..15 (8 d each)
    int bgr = blockIdx.x >> 4;            // b-group 0..7 (32 b each)
    int tid = threadIdx.x, w = tid >> 5, lane = tid & 31;

    // stage W rows [ds*8, ds*8+8) -- coalesced, 16 float4 per thread
    {
        const float4* w4 = (const float4*)W;
        const float4* src = w4 + (size_t)(ds * 8) * (DIN_ / 4);
#pragma unroll
        for (int i = 0; i < 16; i++)
            sW4[i * 256 + tid] = src[i * 256 + tid];
    }
    __syncthreads();

    // mainloop: 4 b-rows per warp, 8 d each, K=2048 via 16 iters of 128
    int b0 = bgr * 32 + w * 4;
    const float4* o4 = (const float4*)outputs;

    float acc[4][8];
#pragma unroll
    for (int bi = 0; bi < 4; bi++)
#pragma unroll
        for (int dd = 0; dd < 8; dd++) acc[bi][dd] = 0.0f;

#pragma unroll 4
    for (int it = 0; it < 16; it++) {
        float4 ov[4];
#pragma unroll
        for (int bi = 0; bi < 4; bi++)
            ov[bi] = o4[(size_t)(b0 + bi) * (DIN_ / 4) + it * 32 + lane];
#pragma unroll
        for (int dd = 0; dd < 8; dd++) {
            float4 wv = sW4[dd * 512 + it * 32 + lane];
#pragma unroll
            for (int bi = 0; bi < 4; bi++) {
                float a = acc[bi][dd];
                a = fmaf(wv.x, ov[bi].x, a);
                a = fmaf(wv.y, ov[bi].y, a);
                a = fmaf(wv.z, ov[bi].z, a);
                a = fmaf(wv.w, ov[bi].w, a);
                acc[bi][dd] = a;
            }
        }
    }

    // reduce all 32 accs across lanes; lane bi*8+dd keeps its value
    float mine = 0.0f;
#pragma unroll
    for (int bi = 0; bi < 4; bi++)
#pragma unroll
        for (int dd = 0; dd < 8; dd++) {
            float r = acc[bi][dd];
#pragma unroll
            for (int o = 16; o; o >>= 1) r += __shfl_xor_sync(FULL, r, o);
            if (lane == bi * 8 + dd) mine = r;
        }

    int dd_l = lane & 7, bi_l = lane >> 3;
    int d = ds * 8 + dd_l;
    int b = b0 + bi_l;
    mine += bias[d];
    g_raw[b * D_ + d] = mine;

    // partial sum-of-squares over this slice's 8 d (within 8-lane groups)
    float sq = mine * mine;
    sq += __shfl_xor_sync(FULL, sq, 1);
    sq += __shfl_xor_sync(FULL, sq, 2);
    sq += __shfl_xor_sync(FULL, sq, 4);
    if (dd_l == 0) g_pssq[b * 16 + ds] = sq;

    if (blockIdx.x == 0 && tid == 0) { g_acc[0] = 0.0f; g_acc[1] = 0.0f; }
}

// ---------------- B: main gather + logsumexp + losses + entries --------------
// One block per batch row. 16 warps; warp w handles negs [w*256, w*256+256).
__global__ void __launch_bounds__(512, 2) kMain(
    const float* __restrict__ mbank,
    const int*   __restrict__ indices,
    const int*   __restrict__ ridx,
    float*       __restrict__ out) {
    int b = blockIdx.x;
    int tid = threadIdx.x, w = tid >> 5, lane = tid & 31;

    __shared__ float sneg[M_];
    __shared__ float sr[33];

    // normalize e on load: ssq = sum of 16 slice partials
    float ssq = (lane < 16) ? g_pssq[b * 16 + lane] : 0.0f;
#pragma unroll
    for (int o = 8; o; o >>= 1) ssq += __shfl_xor_sync(FULL, ssq, o);
    ssq = __shfl_sync(FULL, ssq, 0);
    float inv = 1.0f / fmaxf(sqrtf(ssq), 1e-12f);

    float4 e = ((const float4*)g_raw)[b * 32 + lane];
    e.x *= inv; e.y *= inv; e.z *= inv; e.w *= inv;

    const float4* mb4 = (const float4*)mbank;
    const int* ri = ridx + (size_t)b * M_;

    // ---- gather + dot: 256 negs per warp ----
    int m0 = w * 256;
    for (int mb_ = m0; mb_ < m0 + 256; mb_ += 32) {
        int myIdx = ri[mb_ + lane];
#pragma unroll 8
        for (int j = 0; j < 32; j++) {
            int idx = __shfl_sync(FULL, myIdx, j);
            float4 v = mb4[(size_t)idx * 32 + lane];
            float d = v.x * e.x + v.y * e.y;
            d = fmaf(v.z, e.z, d);
            d = fmaf(v.w, e.w, d);
#pragma unroll
            for (int o = 16; o; o >>= 1) d += __shfl_xor_sync(FULL, d, o);
            if (lane == j) sneg[mb_ + j] = d * TAU_INV;
        }
    }
    __syncthreads();

    // ---- each thread owns 8 negs (stride 512, conflict-free) ----
    float vl[8];
    float mx = -3.0e38f;
#pragma unroll
    for (int i = 0; i < 8; i++) {
        vl[i] = sneg[tid + i * 512];
        mx = fmaxf(mx, vl[i]);
    }
#pragma unroll
    for (int o = 16; o; o >>= 1) mx = fmaxf(mx, __shfl_xor_sync(FULL, mx, o));
    if (lane == 0) sr[w] = mx;
    __syncthreads();
    if (w == 0) {
        float t2 = sr[lane & 15];
#pragma unroll
        for (int o = 8; o; o >>= 1) t2 = fmaxf(t2, __shfl_xor_sync(FULL, t2, o));
        if (lane == 0) sr[32] = t2;
    }
    __syncthreads();
    float Mx = sr[32];

    float se = 0.f;
#pragma unroll
    for (int i = 0; i < 8; i++) se += __expf(vl[i] - Mx);
#pragma unroll
    for (int o = 16; o; o >>= 1) se += __shfl_xor_sync(FULL, se, o);
    __syncthreads();
    if (lane == 0) sr[w] = se;
    __syncthreads();
    if (w == 0) {
        float t2 = (lane < 16) ? sr[lane] : 0.f;
#pragma unroll
        for (int o = 8; o; o >>= 1) t2 += __shfl_xor_sync(FULL, t2, o);
        if (lane == 0) sr[32] = Mx + __logf(t2);
    }
    __syncthreads();
    float logC = sr[32];

    // noise loss: sum softplus(neg - logC)
    float ns = 0.f;
#pragma unroll
    for (int i = 0; i < 8; i++) {
        float x = vl[i] - logC;
        ns += (x > 15.f) ? x : log1pf(__expf(x));
    }
#pragma unroll
    for (int o = 16; o; o >>= 1) ns += __shfl_xor_sync(FULL, ns, o);
    __syncthreads();
    if (lane == 0) sr[w] = ns;
    __syncthreads();
    if (w == 0) {
        float t2 = (lane < 16) ? sr[lane] : 0.f;
#pragma unroll
        for (int o = 8; o; o >>= 1) t2 += __shfl_xor_sync(FULL, t2, o);
        if (lane == 0) atomicAdd(&g_acc[1], t2);
    }

    // ---- warp 0: positive term + entries ----
    if (w == 0) {
        int pidx = indices[b];
        float4 p = mb4[(size_t)pidx * 32 + lane];
        float d = p.x * e.x + p.y * e.y;
        d = fmaf(p.z, e.z, d);
        d = fmaf(p.w, e.w, d);
#pragma unroll
        for (int o = 16; o; o >>= 1) d += __shfl_xor_sync(FULL, d, o);
        float pos = d * TAU_INV;

        float4 ent;
        ent.x = 0.5f * (p.x + e.x);
        ent.y = 0.5f * (p.y + e.y);
        ent.z = 0.5f * (p.z + e.z);
        ent.w = 0.5f * (p.w + e.w);
        float nsq = ent.x * ent.x + ent.y * ent.y + ent.z * ent.z + ent.w * ent.w;
#pragma unroll
        for (int o = 16; o; o >>= 1) nsq += __shfl_xor_sync(FULL, nsq, o);
        float inv2 = 1.0f / fmaxf(sqrtf(nsq), 1e-12f);
        ent.x *= inv2; ent.y *= inv2; ent.z *= inv2; ent.w *= inv2;

        int base = 1 + b * D_ + lane * 4;
        out[base + 0] = ent.x;
        out[base + 1] = ent.y;
        out[base + 2] = ent.z;
        out[base + 3] = ent.w;

        if (lane == 0) {
            float x = logC - pos;
            float dl = (x > 15.f) ? x : log1pf(__expf(x));
            atomicAdd(&g_acc[0], dl);
        }
    }
}

// ---------------- C: finalize scalars ----------------------------------------
__global__ void kFinal(float* __restrict__ out) {
    float dl = g_acc[0] * (1.0f / (float)B_);
    float nl = g_acc[1] * (1.0f / (float)B_);
    out[0] = dl + nl;
    out[1 + B_ * D_]     = dl;
    out[1 + B_ * D_ + 1] = nl;
}

// ---------------- launcher ----------------------------------------------------
extern "C" void kernel_launch(void* const* d_in, const int* in_sizes, int n_in,
                              void* d_out, int out_size) {
    const float* outputs = (const float*)d_in[0];
    const float* W       = (const float*)d_in[1];
    const float* bias    = (const float*)d_in[2];
    const float* mbank   = (const float*)d_in[3];
    const int*   indices = (const int*)d_in[4];
    const int*   ridx    = (const int*)d_in[5];
    float* out = (float*)d_out;

    // allow 64 KB dynamic smem for kGemm (idempotent, not an allocation)
    static int smem_set = 0;
    if (!smem_set) {
        cudaFuncSetAttribute(kGemm, cudaFuncAttributeMaxDynamicSharedMemorySize,
                             64 * 1024);
        smem_set = 1;
    }

    kGemm<<<128, 256, 64 * 1024>>>(outputs, W, bias);
    kMain<<<256, 512>>>(mbank, indices, ridx, out);
    kFinal<<<1, 1>>>(out);
}

// round 9
// speedup vs baseline: 1.2937x; 1.0205x over previous
#include <cuda_runtime.h>
#include <cstdint>
#include <math.h>

#define FULL 0xffffffffu

static constexpr int B_   = 256;
static constexpr int D_   = 128;
static constexpr int DIN_ = 2048;
static constexpr int M_   = 4096;
static constexpr float TAU_INV = 1.0f / 0.07f;

// ---------------- device scratch ----------------
__device__ float g_raw[B_ * D_];        // un-normalized emb (+bias), 128 KB
__device__ float g_pssq[B_ * 32];       // per-d-slice partial sum-of-squares
__device__ float g_acc[2];              // [0]=sum data softplus, [1]=sum noise softplus

// ---------------- A: GEMM with W slice in SMEM -------------------------------
// grid 256 = 32 d-slices (4 cols) x 8 b-groups (32 rows). 256 threads = 8 warps,
// 2 blocks/SM. Warp w owns 4 b-rows x 4 d-cols; lanes sweep K via float4.
// W slice (4 x 2048 fp32 = 32 KB) staged once in static smem.
__global__ void __launch_bounds__(256, 2)
kGemm(const float* __restrict__ outputs,
      const float* __restrict__ W,
      const float* __restrict__ bias) {
    __shared__ float4 sW4[4 * 512];       // 32 KB
    int ds  = blockIdx.x & 31;            // d-slice 0..31 (4 d each)
    int bgr = blockIdx.x >> 5;            // b-group 0..7 (32 b each)
    int tid = threadIdx.x, w = tid >> 5, lane = tid & 31;

    // stage W rows [ds*4, ds*4+4) -- coalesced, 8 float4 per thread
    {
        const float4* src = (const float4*)W + (size_t)(ds * 4) * (DIN_ / 4);
#pragma unroll
        for (int i = 0; i < 8; i++)
            sW4[i * 256 + tid] = src[i * 256 + tid];
    }
    __syncthreads();

    // mainloop: 4 b-rows per warp, 4 d each, K=2048 via 16 iters of 128
    int b0 = bgr * 32 + w * 4;
    const float4* o4 = (const float4*)outputs;

    float acc[4][4];
#pragma unroll
    for (int bi = 0; bi < 4; bi++)
#pragma unroll
        for (int dd = 0; dd < 4; dd++) acc[bi][dd] = 0.0f;

#pragma unroll 4
    for (int it = 0; it < 16; it++) {
        float4 ov[4];
#pragma unroll
        for (int bi = 0; bi < 4; bi++)
            ov[bi] = o4[(size_t)(b0 + bi) * (DIN_ / 4) + it * 32 + lane];
#pragma unroll
        for (int dd = 0; dd < 4; dd++) {
            float4 wv = sW4[dd * 512 + it * 32 + lane];
#pragma unroll
            for (int bi = 0; bi < 4; bi++) {
                float a = acc[bi][dd];
                a = fmaf(wv.x, ov[bi].x, a);
                a = fmaf(wv.y, ov[bi].y, a);
                a = fmaf(wv.z, ov[bi].z, a);
                a = fmaf(wv.w, ov[bi].w, a);
                acc[bi][dd] = a;
            }
        }
    }

    // reduce all 16 accs across lanes; lane bi*4+dd keeps its value
    float mine = 0.0f;
#pragma unroll
    for (int bi = 0; bi < 4; bi++)
#pragma unroll
        for (int dd = 0; dd < 4; dd++) {
            float r = acc[bi][dd];
#pragma unroll
            for (int o = 16; o; o >>= 1) r += __shfl_xor_sync(FULL, r, o);
            if (lane == bi * 4 + dd) mine = r;
        }

    if (lane < 16) {
        int dd_l = lane & 3, bi_l = lane >> 2;
        int d = ds * 4 + dd_l;
        int b = b0 + bi_l;
        mine += bias[d];
        g_raw[b * D_ + d] = mine;

        // partial sum-of-squares over this slice's 4 d (4-lane groups)
        float sq = mine * mine;
        sq += __shfl_xor_sync(0x0000ffffu, sq, 1);
        sq += __shfl_xor_sync(0x0000ffffu, sq, 2);
        if (dd_l == 0) g_pssq[b * 32 + ds] = sq;
    }

    if (blockIdx.x == 0 && tid == 0) { g_acc[0] = 0.0f; g_acc[1] = 0.0f; }
}

// ---------------- B: main gather + logsumexp + losses + entries --------------
// One block per batch row. 16 warps; warp w handles negs [w*256, w*256+256).
__global__ void __launch_bounds__(512, 2) kMain(
    const float* __restrict__ mbank,
    const int*   __restrict__ indices,
    const int*   __restrict__ ridx,
    float*       __restrict__ out) {
    int b = blockIdx.x;
    int tid = threadIdx.x, w = tid >> 5, lane = tid & 31;

    __shared__ float sneg[M_];
    __shared__ float sr[33];

    // normalize e on load: ssq = sum of 32 slice partials
    float ssq = g_pssq[b * 32 + lane];
#pragma unroll
    for (int o = 16; o; o >>= 1) ssq += __shfl_xor_sync(FULL, ssq, o);
    float inv = 1.0f / fmaxf(sqrtf(ssq), 1e-12f);

    float4 e = ((const float4*)g_raw)[b * 32 + lane];
    e.x *= inv; e.y *= inv; e.z *= inv; e.w *= inv;

    const float4* mb4 = (const float4*)mbank;
    const int* ri = ridx + (size_t)b * M_;

    // ---- gather + dot: 256 negs per warp ----
    int m0 = w * 256;
    for (int mb_ = m0; mb_ < m0 + 256; mb_ += 32) {
        int myIdx = ri[mb_ + lane];
#pragma unroll 8
        for (int j = 0; j < 32; j++) {
            int idx = __shfl_sync(FULL, myIdx, j);
            float4 v = mb4[(size_t)idx * 32 + lane];
            float d = v.x * e.x + v.y * e.y;
            d = fmaf(v.z, e.z, d);
            d = fmaf(v.w, e.w, d);
#pragma unroll
            for (int o = 16; o; o >>= 1) d += __shfl_xor_sync(FULL, d, o);
            if (lane == j) sneg[mb_ + j] = d * TAU_INV;
        }
    }
    __syncthreads();

    // ---- each thread owns 8 negs (stride 512, conflict-free) ----
    float vl[8];
    float mx = -3.0e38f;
#pragma unroll
    for (int i = 0; i < 8; i++) {
        vl[i] = sneg[tid + i * 512];
        mx = fmaxf(mx, vl[i]);
    }
#pragma unroll
    for (int o = 16; o; o >>= 1) mx = fmaxf(mx, __shfl_xor_sync(FULL, mx, o));
    if (lane == 0) sr[w] = mx;
    __syncthreads();
    if (w == 0) {
        float t2 = sr[lane & 15];
#pragma unroll
        for (int o = 8; o; o >>= 1) t2 = fmaxf(t2, __shfl_xor_sync(FULL, t2, o));
        if (lane == 0) sr[32] = t2;
    }
    __syncthreads();
    float Mx = sr[32];

    float se = 0.f;
#pragma unroll
    for (int i = 0; i < 8; i++) se += __expf(vl[i] - Mx);
#pragma unroll
    for (int o = 16; o; o >>= 1) se += __shfl_xor_sync(FULL, se, o);
    __syncthreads();
    if (lane == 0) sr[w] = se;
    __syncthreads();
    if (w == 0) {
        float t2 = (lane < 16) ? sr[lane] : 0.f;
#pragma unroll
        for (int o = 8; o; o >>= 1) t2 += __shfl_xor_sync(FULL, t2, o);
        if (lane == 0) sr[32] = Mx + __logf(t2);
    }
    __syncthreads();
    float logC = sr[32];

    // noise loss: sum softplus(neg - logC)
    float ns = 0.f;
#pragma unroll
    for (int i = 0; i < 8; i++) {
        float x = vl[i] - logC;
        ns += (x > 15.f) ? x : log1pf(__expf(x));
    }
#pragma unroll
    for (int o = 16; o; o >>= 1) ns += __shfl_xor_sync(FULL, ns, o);
    __syncthreads();
    if (lane == 0) sr[w] = ns;
    __syncthreads();
    if (w == 0) {
        float t2 = (lane < 16) ? sr[lane] : 0.f;
#pragma unroll
        for (int o = 8; o; o >>= 1) t2 += __shfl_xor_sync(FULL, t2, o);
        if (lane == 0) atomicAdd(&g_acc[1], t2);
    }

    // ---- warp 0: positive term + entries ----
    if (w == 0) {
        int pidx = indices[b];
        float4 p = mb4[(size_t)pidx * 32 + lane];
        float d = p.x * e.x + p.y * e.y;
        d = fmaf(p.z, e.z, d);
        d = fmaf(p.w, e.w, d);
#pragma unroll
        for (int o = 16; o; o >>= 1) d += __shfl_xor_sync(FULL, d, o);
        float pos = d * TAU_INV;

        float4 ent;
        ent.x = 0.5f * (p.x + e.x);
        ent.y = 0.5f * (p.y + e.y);
        ent.z = 0.5f * (p.z + e.z);
        ent.w = 0.5f * (p.w + e.w);
        float nsq = ent.x * ent.x + ent.y * ent.y + ent.z * ent.z + ent.w * ent.w;
#pragma unroll
        for (int o = 16; o; o >>= 1) nsq += __shfl_xor_sync(FULL, nsq, o);
        float inv2 = 1.0f / fmaxf(sqrtf(nsq), 1e-12f);
        ent.x *= inv2; ent.y *= inv2; ent.z *= inv2; ent.w *= inv2;

        int base = 1 + b * D_ + lane * 4;
        out[base + 0] = ent.x;
        out[base + 1] = ent.y;
        out[base + 2] = ent.z;
        out[base + 3] = ent.w;

        if (lane == 0) {
            float x = logC - pos;
            float dl = (x > 15.f) ? x : log1pf(__expf(x));
            atomicAdd(&g_acc[0], dl);
        }
    }
}

// ---------------- C: finalize scalars ----------------------------------------
__global__ void kFinal(float* __restrict__ out) {
    float dl = g_acc[0] * (1.0f / (float)B_);
    float nl = g_acc[1] * (1.0f / (float)B_);
    out[0] = dl + nl;
    out[1 + B_ * D_]     = dl;
    out[1 + B_ * D_ + 1] = nl;
}

// ---------------- launcher ----------------------------------------------------
extern "C" void kernel_launch(void* const* d_in, const int* in_sizes, int n_in,
                              void* d_out, int out_size) {
    const float* outputs = (const float*)d_in[0];
    const float* W       = (const float*)d_in[1];
    const float* bias    = (const float*)d_in[2];
    const float* mbank   = (const float*)d_in[3];
    const int*   indices = (const int*)d_in[4];
    const int*   ridx    = (const int*)d_in[5];
    float* out = (float*)d_out;

    kGemm<<<256, 256>>>(outputs, W, bias);
    kMain<<<256, 512>>>(mbank, indices, ridx, out);
    kFinal<<<1, 1>>>(out);
}